// round 11
// baseline (speedup 1.0000x reference)
#include <cuda_runtime.h>
#include <cuda_bf16.h>

#define BATCH 2
#define CDIM  256
#define HWN   16384
#define NKEY  4224
#define FDIM  1024
#define NQC   (BATCH*HWN*CDIM)
#define NKC   (BATCH*NKEY*CDIM)
#define MROWS (BATCH*HWN)
#define KROWS (BATCH*NKEY)

#define OFF_X    0
#define OFF_X2   (OFF_X + NQC)
#define OFF_Y    (OFF_X2 + NQC)
#define OFF_SEM  (OFF_Y + NQC)
#define OFF_LNB  (OFF_SEM + BATCH*NKEY + 64)
#define OFF_QB   (OFF_LNB + NQC/2)
#define OFF_ATTB (OFF_QB + NQC/2)
#define OFF_HB   (OFF_ATTB + NQC/2)
#define OFF_KEYB (OFF_HB + (BATCH*HWN*FDIM)/2)
#define OFF_VALB (OFF_KEYB + NKC/2)
#define OFF_KB   (OFF_VALB + NKC/2)
#define OFF_VB   (OFF_KB + NKC/2)
#define OFF_WB   (OFF_VB + NKC/2)
#define SCRATCH_FLOATS (OFF_WB + 786432/2 + 64)

__device__ float g_scratch[SCRATCH_FLOATS];

// ---------------- PTX helpers (mma.sync only — sm_100 target, no tcgen05) ----
__device__ __forceinline__ unsigned smem_u32(const void* p) {
    return (unsigned)__cvta_generic_to_shared(p);
}
__device__ __forceinline__ void ldmx4(unsigned& r0, unsigned& r1, unsigned& r2,
                                      unsigned& r3, const void* p) {
    unsigned a = smem_u32(p);
    asm volatile("ldmatrix.sync.aligned.m8n8.x4.shared.b16 {%0,%1,%2,%3},[%4];\n"
                 : "=r"(r0), "=r"(r1), "=r"(r2), "=r"(r3) : "r"(a));
}
__device__ __forceinline__ void ldmx4t(unsigned& r0, unsigned& r1, unsigned& r2,
                                       unsigned& r3, const void* p) {
    unsigned a = smem_u32(p);
    asm volatile("ldmatrix.sync.aligned.m8n8.x4.trans.shared.b16 {%0,%1,%2,%3},[%4];\n"
                 : "=r"(r0), "=r"(r1), "=r"(r2), "=r"(r3) : "r"(a));
}
__device__ __forceinline__ void mma16816(float* c, const unsigned* a, const unsigned* b) {
    asm volatile("mma.sync.aligned.m16n8k16.row.col.f32.bf16.bf16.f32 "
                 "{%0,%1,%2,%3},{%4,%5,%6,%7},{%8,%9},{%0,%1,%2,%3};\n"
                 : "+f"(c[0]), "+f"(c[1]), "+f"(c[2]), "+f"(c[3])
                 : "r"(a[0]), "r"(a[1]), "r"(a[2]), "r"(a[3]), "r"(b[0]), "r"(b[1]));
}
__device__ __forceinline__ void cp16(void* dst, const void* src) {
    unsigned d = smem_u32(dst);
    asm volatile("cp.async.cg.shared.global [%0],[%1],16;\n" :: "r"(d), "l"(src));
}
__device__ __forceinline__ void cp_commit() {
    asm volatile("cp.async.commit_group;\n" ::: "memory");
}
template <int N>
__device__ __forceinline__ void cp_wait() {
    asm volatile("cp.async.wait_group %0;\n" :: "n"(N) : "memory");
}
__device__ __forceinline__ unsigned pack_bf2(float x, float y) {
    __nv_bfloat162 h = __floats2bfloat162_rn(x, y);
    return *reinterpret_cast<unsigned*>(&h);
}

// ---------------- elementwise kernels ----------------
__global__ void wcvt_k(const float* __restrict__ Wq, const float* __restrict__ Wk,
                       const float* __restrict__ Wv, const float* __restrict__ Wp,
                       const float* __restrict__ W1, const float* __restrict__ W2,
                       __nv_bfloat16* __restrict__ out)
{
    int i = (blockIdx.x * blockDim.x + threadIdx.x) * 4;
    if (i >= 786432) return;
    const float* src; int base;
    if      (i < 65536)  { src = Wq; base = 0; }
    else if (i < 131072) { src = Wk; base = 65536; }
    else if (i < 196608) { src = Wv; base = 131072; }
    else if (i < 262144) { src = Wp; base = 196608; }
    else if (i < 524288) { src = W1; base = 262144; }
    else                 { src = W2; base = 524288; }
    float4 v = *(const float4*)(src + (i - base));
    *(__nv_bfloat162*)(out + i)     = __floats2bfloat162_rn(v.x, v.y);
    *(__nv_bfloat162*)(out + i + 2) = __floats2bfloat162_rn(v.z, v.w);
}

__global__ void kvsem_k(const float* __restrict__ key, const float* __restrict__ value,
                        const float* __restrict__ Wsem, const float* __restrict__ bsem,
                        __nv_bfloat16* __restrict__ keyb, __nv_bfloat16* __restrict__ valb,
                        float* __restrict__ sem)
{
    int w = blockIdx.x * 8 + (threadIdx.x >> 5);
    int lane = threadIdx.x & 31;
    if (w >= KROWS) return;
    int c0 = lane * 8;
    float4 ws0 = *(const float4*)(Wsem + c0);
    float4 ws1 = *(const float4*)(Wsem + c0 + 4);
    {
        const float4* kr = (const float4*)(key + (size_t)w * CDIM + c0);
        float4 a = kr[0], b = kr[1];
        __nv_bfloat162* d = (__nv_bfloat162*)(keyb + (size_t)w * CDIM + c0);
        d[0] = __floats2bfloat162_rn(a.x, a.y);
        d[1] = __floats2bfloat162_rn(a.z, a.w);
        d[2] = __floats2bfloat162_rn(b.x, b.y);
        d[3] = __floats2bfloat162_rn(b.z, b.w);
    }
    {
        const float4* vr = (const float4*)(value + (size_t)w * CDIM + c0);
        float4 a = vr[0], b = vr[1];
        __nv_bfloat162* d = (__nv_bfloat162*)(valb + (size_t)w * CDIM + c0);
        d[0] = __floats2bfloat162_rn(a.x, a.y);
        d[1] = __floats2bfloat162_rn(a.z, a.w);
        d[2] = __floats2bfloat162_rn(b.x, b.y);
        d[3] = __floats2bfloat162_rn(b.z, b.w);
        float acc = a.x * ws0.x + a.y * ws0.y + a.z * ws0.z + a.w * ws0.w
                  + b.x * ws1.x + b.y * ws1.y + b.z * ws1.z + b.w * ws1.w;
#pragma unroll
        for (int off = 16; off; off >>= 1)
            acc += __shfl_xor_sync(0xffffffffu, acc, off);
        if (lane == 0) sem[w] = acc + bsem[0];
    }
}

#define TQP 261
__global__ __launch_bounds__(256)
void tq_ln_k(const float* __restrict__ query, const float* __restrict__ g,
             const float* __restrict__ bb, float* __restrict__ X,
             __nv_bfloat16* __restrict__ LNB)
{
    __shared__ float sm[32][TQP];
    const int tx = threadIdx.x & 31, ty = threadIdx.x >> 5;
    const int b = blockIdx.y;
    const int n0 = blockIdx.x * 32;
    const float* qb = query + (size_t)b * CDIM * HWN;
#pragma unroll
    for (int i = 0; i < 8; i++)
#pragma unroll
        for (int j = 0; j < 4; j++) {
            int c = i * 32 + ty + j * 8;
            sm[tx][c] = qb[(size_t)c * HWN + n0 + tx];
        }
    __syncthreads();
    const int w = ty, lane = tx;
    float gv[8], bv[8];
#pragma unroll
    for (int j = 0; j < 8; j++) { gv[j] = g[lane * 8 + j]; bv[j] = bb[lane * 8 + j]; }
#pragma unroll
    for (int q = 0; q < 4; q++) {
        int nl = w * 4 + q;
        float v[8];
#pragma unroll
        for (int j = 0; j < 8; j++) v[j] = sm[nl][lane * 8 + j];
        float s = 0.f, s2 = 0.f;
#pragma unroll
        for (int j = 0; j < 8; j++) { s += v[j]; s2 += v[j] * v[j]; }
#pragma unroll
        for (int off = 16; off; off >>= 1) {
            s  += __shfl_xor_sync(0xffffffffu, s,  off);
            s2 += __shfl_xor_sync(0xffffffffu, s2, off);
        }
        float mu  = s * (1.f / CDIM);
        float var = s2 * (1.f / CDIM) - mu * mu;
        float rs  = rsqrtf(var + 1e-5f);
        size_t rowoff = (size_t)(b * HWN + n0 + nl) * CDIM + lane * 8;
        *(float4*)(X + rowoff)     = make_float4(v[0], v[1], v[2], v[3]);
        *(float4*)(X + rowoff + 4) = make_float4(v[4], v[5], v[6], v[7]);
        __nv_bfloat162* d = (__nv_bfloat162*)(LNB + rowoff);
#pragma unroll
        for (int j = 0; j < 4; j++) {
            float o0 = (v[2 * j]     - mu) * rs * gv[2 * j]     + bv[2 * j];
            float o1 = (v[2 * j + 1] - mu) * rs * gv[2 * j + 1] + bv[2 * j + 1];
            d[j] = __floats2bfloat162_rn(o0, o1);
        }
    }
}

__global__ void ln2_k(const float* __restrict__ in, const float* __restrict__ g,
                      const float* __restrict__ bb, __nv_bfloat16* __restrict__ out)
{
    int w = blockIdx.x * 8 + (threadIdx.x >> 5);
    int lane = threadIdx.x & 31;
    int c0 = lane * 8;
    const float4* ir = (const float4*)(in + (size_t)w * CDIM + c0);
    float4 a = ir[0], bq = ir[1];
    float v[8] = {a.x, a.y, a.z, a.w, bq.x, bq.y, bq.z, bq.w};
    float s = 0.f, s2 = 0.f;
#pragma unroll
    for (int j = 0; j < 8; j++) { s += v[j]; s2 += v[j] * v[j]; }
#pragma unroll
    for (int off = 16; off; off >>= 1) {
        s  += __shfl_xor_sync(0xffffffffu, s,  off);
        s2 += __shfl_xor_sync(0xffffffffu, s2, off);
    }
    float mu  = s * (1.f / CDIM);
    float var = s2 * (1.f / CDIM) - mu * mu;
    float rs  = rsqrtf(var + 1e-5f);
    __nv_bfloat162* d = (__nv_bfloat162*)(out + (size_t)w * CDIM + c0);
#pragma unroll
    for (int j = 0; j < 4; j++) {
        float o0 = (v[2 * j]     - mu) * rs * g[c0 + 2 * j]     + bb[c0 + 2 * j];
        float o1 = (v[2 * j + 1] - mu) * rs * g[c0 + 2 * j + 1] + bb[c0 + 2 * j + 1];
        d[j] = __floats2bfloat162_rn(o0, o1);
    }
}

__global__ void transpose_k(const float* __restrict__ in, float* __restrict__ out,
                            int R, int S)
{
    __shared__ float tile[32][33];
    const float* ip = in  + (size_t)blockIdx.z * R * S;
    float*       op = out + (size_t)blockIdx.z * R * S;
    int r0 = blockIdx.y * 32, s0 = blockIdx.x * 32;
    int tx = threadIdx.x, ty = threadIdx.y;
#pragma unroll
    for (int i = ty; i < 32; i += 8)
        tile[i][tx] = ip[(size_t)(r0 + i) * S + s0 + tx];
    __syncthreads();
#pragma unroll
    for (int i = ty; i < 32; i += 8)
        op[(size_t)(s0 + i) * R + r0 + tx] = tile[tx][i];
}

// ---------------- mma.sync GEMM: BM=BN=128, BK=32, 4-stage cp.async ----------------
#define GAP   40    // As pitch (bf16), 32 cols + 8 pad
#define GBP   136   // Bs pitch (bf16)
#define AS_STG (128 * GAP)                  // elems per stage
#define BS_STG (32 * GBP)
#define GEMM_SMEM ((4 * AS_STG + 4 * BS_STG) * 2)   // 75776 bytes

template <int MODE>
__device__ __forceinline__
void mgemm_body(const __nv_bfloat16* __restrict__ A, const __nv_bfloat16* __restrict__ Bm,
                const float* __restrict__ bias, const float* __restrict__ resid,
                float* __restrict__ Cf, __nv_bfloat16* __restrict__ Cb,
                int M, int N, int K)
{
    extern __shared__ __nv_bfloat16 gsm[];
    __nv_bfloat16* As = gsm;                   // [4][128][GAP]
    __nv_bfloat16* Bs = gsm + 4 * AS_STG;      // [4][32][GBP]

    const int tid  = threadIdx.x;
    const int lane = tid & 31, w = tid >> 5;
    const int wm = w >> 1, wn = w & 1;
    const int sub = lane >> 3, l8 = lane & 7;
    const int bm = blockIdx.y * 128, bn = blockIdx.x * 128;

    const int a_row  = wm * 32 + (sub & 1) * 8 + l8;
    const int a_csel = (sub >> 1) * 8;
    const int b_rsel = (sub & 1) * 8 + l8;
    const int b_csel = wn * 64 + (sub >> 1) * 8;

    float C[2][8][4];
#pragma unroll
    for (int i = 0; i < 2; i++)
#pragma unroll
        for (int j = 0; j < 8; j++)
#pragma unroll
            for (int q = 0; q < 4; q++) C[i][j][q] = 0.f;

    const int KT = K / 32;

    auto load_stage = [&](int s, int k0) {
        __nv_bfloat16* Ast = As + s * AS_STG;
        __nv_bfloat16* Bst = Bs + s * BS_STG;
#pragma unroll
        for (int i = 0; i < 2; i++) {            // A: 512 chunks (128x32)
            int ch = tid + i * 256;
            int ar = ch >> 2, ac = (ch & 3) * 8;
            cp16(&Ast[ar * GAP + ac], A + (size_t)(bm + ar) * K + k0 + ac);
        }
#pragma unroll
        for (int i = 0; i < 2; i++) {            // B: 512 chunks (32x128)
            int ch = tid + i * 256;
            int br = ch >> 4, bc = (ch & 15) * 8;
            cp16(&Bst[br * GBP + bc], Bm + (size_t)(k0 + br) * N + bn + bc);
        }
    };

    // prologue: stages 0..2 (3 groups in flight)
#pragma unroll
    for (int s = 0; s < 3; s++) { load_stage(s, s * 32); cp_commit(); }

    for (int kt = 0; kt < KT; kt++) {
        cp_wait<2>();          // stage kt complete (2 newer groups may be in flight)
        __syncthreads();       // all warps done with stage kt-1 -> slot (kt+3)&3 free
        if (kt + 3 < KT) load_stage((kt + 3) & 3, (kt + 3) * 32);
        cp_commit();           // exactly one group per iteration (possibly empty)

        const __nv_bfloat16* Ast = As + (kt & 3) * AS_STG;
        const __nv_bfloat16* Bst = Bs + (kt & 3) * BS_STG;
#pragma unroll
        for (int kf = 0; kf < 2; kf++) {
            unsigned a[2][4];
#pragma unroll
            for (int mf = 0; mf < 2; mf++)
                ldmx4(a[mf][0], a[mf][1], a[mf][2], a[mf][3],
                      &Ast[(a_row + mf * 16) * GAP + kf * 16 + a_csel]);
            unsigned b[8][2];
#pragma unroll
            for (int nb = 0; nb < 4; nb++) {
                unsigned r0, r1, r2, r3;
                ldmx4t(r0, r1, r2, r3, &Bst[(kf * 16 + b_rsel) * GBP + b_csel + nb * 16]);
                b[2 * nb][0] = r0; b[2 * nb][1] = r1;
                b[2 * nb + 1][0] = r2; b[2 * nb + 1][1] = r3;
            }
#pragma unroll
            for (int mf = 0; mf < 2; mf++)
#pragma unroll
                for (int nf = 0; nf < 8; nf++)
                    mma16816(C[mf][nf], a[mf], b[nf]);
        }
    }
    __syncthreads();

    // epilogue
#pragma unroll
    for (int mf = 0; mf < 2; mf++) {
        int row0 = bm + wm * 32 + mf * 16 + (lane >> 2);
#pragma unroll
        for (int nf = 0; nf < 8; nf++) {
            int col = bn + wn * 64 + nf * 8 + (lane & 3) * 2;
            float b0 = bias ? bias[col] : 0.f;
            float b1 = bias ? bias[col + 1] : 0.f;
#pragma unroll
            for (int half = 0; half < 2; half++) {
                int row = row0 + half * 8;
                float v0 = C[mf][nf][2 * half]     + b0;
                float v1 = C[mf][nf][2 * half + 1] + b1;
                if (MODE == 3) {
                    float2 r = *(const float2*)(resid + (size_t)row * N + col);
                    v0 += r.x; v1 += r.y;
                    *(float2*)(Cf + (size_t)row * N + col) = make_float2(v0, v1);
                } else if (MODE == 4) {
                    v0 = 0.5f * v0 * (1.f + erff(v0 * 0.70710678118654752f));
                    v1 = 0.5f * v1 * (1.f + erff(v1 * 0.70710678118654752f));
                    *(__nv_bfloat162*)(Cb + (size_t)row * N + col) = __floats2bfloat162_rn(v0, v1);
                } else {
                    *(__nv_bfloat162*)(Cb + (size_t)row * N + col) = __floats2bfloat162_rn(v0, v1);
                }
            }
        }
    }
}

template <int MODE>
__global__ __launch_bounds__(256)
void mgemm_k(const __nv_bfloat16* __restrict__ A, const __nv_bfloat16* __restrict__ Bm,
             const float* __restrict__ bias, const float* __restrict__ resid,
             float* __restrict__ Cf, __nv_bfloat16* __restrict__ Cb,
             int M, int N, int K)
{
    mgemm_body<MODE>(A, Bm, bias, resid, Cf, Cb, M, N, K);
}

__global__ __launch_bounds__(256)
void kvgemm_k(const __nv_bfloat16* __restrict__ A0, const __nv_bfloat16* __restrict__ A1,
              const __nv_bfloat16* __restrict__ B0, const __nv_bfloat16* __restrict__ B1,
              const float* __restrict__ bias1,
              __nv_bfloat16* __restrict__ C0, __nv_bfloat16* __restrict__ C1)
{
    if (blockIdx.z == 0)
        mgemm_body<1>(A0, B0, nullptr, nullptr, nullptr, C0, KROWS, CDIM, CDIM);
    else
        mgemm_body<1>(A1, B1, bias1, nullptr, nullptr, C1, KROWS, CDIM, CDIM);
}

// ---------------------------------------------------------------------------
// Flash attention (mma.sync, MAX-FREE softmax). Br=128 (8 warps x 16 rows),
// Bc=64, d=256. Unchanged from the 780us kernel.
// ---------------------------------------------------------------------------
#define APITCH 264
#define QELEMS (128 * APITCH)
#define KVELEMS (64 * APITCH)
#define ATT_SMEM ((QELEMS + 4 * KVELEMS) * 2 + 2 * 64 * 4)

__global__ __launch_bounds__(256, 1)
void fattn_k(const __nv_bfloat16* __restrict__ gq, const __nv_bfloat16* __restrict__ gk,
             const __nv_bfloat16* __restrict__ gv, const float* __restrict__ gsem,
             __nv_bfloat16* __restrict__ gout)
{
    extern __shared__ char smraw[];
    __nv_bfloat16* Qs = (__nv_bfloat16*)smraw;
    __nv_bfloat16* Ks = Qs + QELEMS;                  // [2][64][APITCH]
    __nv_bfloat16* Vs = Ks + 2 * KVELEMS;             // [2][64][APITCH]
    float*         semS = (float*)(Vs + 2 * KVELEMS); // [2][64]

    const int tid  = threadIdx.x;
    const int lane = tid & 31, w = tid >> 5;
    const int sub  = lane >> 3, l8 = lane & 7;
    const int b    = blockIdx.y;
    const int qrow0 = b * HWN + blockIdx.x * 128;

    const int q_row  = w * 16 + (sub & 1) * 8 + l8;
    const int q_csel = (sub >> 1) * 8;
    const int k_rsel = (sub & 1) * 8 + l8;
    const int k_csel = (sub >> 1) * 8;

#pragma unroll
    for (int i = 0; i < 16; i++) {
        int ch = tid + i * 256;
        int r = ch >> 5, c = (ch & 31) * 8;
        cp16(&Qs[r * APITCH + c], gq + (size_t)(qrow0 + r) * CDIM + c);
    }
    const size_t kvbase = (size_t)b * NKEY;
#pragma unroll
    for (int i = 0; i < 8; i++) {
        int ch = tid + i * 256;
        int r = ch >> 5, c = (ch & 31) * 8;
        cp16(&Ks[r * APITCH + c], gk + (kvbase + r) * CDIM + c);
        cp16(&Vs[r * APITCH + c], gv + (kvbase + r) * CDIM + c);
    }
    if (tid < 16) cp16(&semS[tid * 4], gsem + kvbase + tid * 4);
    cp_commit();

    float O[32][4];
#pragma unroll
    for (int i = 0; i < 32; i++)
#pragma unroll
        for (int j = 0; j < 4; j++) O[i][j] = 0.f;
    float l0 = 0.f, l1 = 0.f;

    const int T = NKEY / 64;   // 66
    for (int t = 0; t < T; t++) {
        const int s = t & 1;
        if (t + 1 < T) {
            const int s2 = (t + 1) & 1;
            const size_t rb = kvbase + (size_t)(t + 1) * 64;
#pragma unroll
            for (int i = 0; i < 8; i++) {
                int ch = tid + i * 256;
                int r = ch >> 5, c = (ch & 31) * 8;
                cp16(&Ks[s2 * KVELEMS + r * APITCH + c], gk + (rb + r) * CDIM + c);
                cp16(&Vs[s2 * KVELEMS + r * APITCH + c], gv + (rb + r) * CDIM + c);
            }
            if (tid < 16) cp16(&semS[s2 * 64 + tid * 4], gsem + rb + tid * 4);
            cp_commit();
            cp_wait<1>();
        } else {
            cp_wait<0>();
        }
        __syncthreads();

        float S[8][4];
#pragma unroll
        for (int i = 0; i < 8; i++)
#pragma unroll
            for (int j = 0; j < 4; j++) S[i][j] = 0.f;
        const __nv_bfloat16* Kt = Ks + s * KVELEMS;
#pragma unroll
        for (int kf = 0; kf < 16; kf++) {
            unsigned a[4];
            ldmx4(a[0], a[1], a[2], a[3], &Qs[q_row * APITCH + kf * 16 + q_csel]);
#pragma unroll
            for (int nb = 0; nb < 4; nb++) {
                unsigned r0, r1, r2, r3;
                ldmx4(r0, r1, r2, r3,
                      &Kt[(nb * 16 + k_rsel) * APITCH + kf * 16 + k_csel]);
                unsigned bA[2] = {r0, r2};
                unsigned bB[2] = {r1, r3};
                mma16816(S[2 * nb], a, bA);
                mma16816(S[2 * nb + 1], a, bB);
            }
        }

        const float* semT = semS + s * 64;
        unsigned PA[4][4];
#pragma unroll
        for (int kf = 0; kf < 4; kf++) {
            int c0a = (2 * kf) * 8 + (lane & 3) * 2;
            int c0b = (2 * kf + 1) * 8 + (lane & 3) * 2;
            float p00 = __expf(S[2 * kf][0] * 0.0625f + semT[c0a]);
            float p01 = __expf(S[2 * kf][1] * 0.0625f + semT[c0a + 1]);
            float p02 = __expf(S[2 * kf][2] * 0.0625f + semT[c0a]);
            float p03 = __expf(S[2 * kf][3] * 0.0625f + semT[c0a + 1]);
            float p10 = __expf(S[2 * kf + 1][0] * 0.0625f + semT[c0b]);
            float p11 = __expf(S[2 * kf + 1][1] * 0.0625f + semT[c0b + 1]);
            float p12 = __expf(S[2 * kf + 1][2] * 0.0625f + semT[c0b]);
            float p13 = __expf(S[2 * kf + 1][3] * 0.0625f + semT[c0b + 1]);
            l0 += p00 + p01 + p10 + p11;
            l1 += p02 + p03 + p12 + p13;
            PA[kf][0] = pack_bf2(p00, p01);
            PA[kf][1] = pack_bf2(p02, p03);
            PA[kf][2] = pack_bf2(p10, p11);
            PA[kf][3] = pack_bf2(p12, p13);
        }

        const __nv_bfloat16* Vt = Vs + s * KVELEMS;
#pragma unroll
        for (int db = 0; db < 16; db++) {
#pragma unroll
            for (int kf = 0; kf < 4; kf++) {
                unsigned r0, r1, r2, r3;
                ldmx4t(r0, r1, r2, r3,
                       &Vt[(kf * 16 + k_rsel) * APITCH + db * 16 + k_csel]);
                unsigned bA[2] = {r0, r1};
                unsigned bB[2] = {r2, r3};
                mma16816(O[2 * db], PA[kf], bA);
                mma16816(O[2 * db + 1], PA[kf], bB);
            }
        }
        __syncthreads();
    }

    l0 += __shfl_xor_sync(0xffffffffu, l0, 1);
    l0 += __shfl_xor_sync(0xffffffffu, l0, 2);
    l1 += __shfl_xor_sync(0xffffffffu, l1, 1);
    l1 += __shfl_xor_sync(0xffffffffu, l1, 2);
    float inv0 = 1.f / l0, inv1 = 1.f / l1;
    int row0 = qrow0 + w * 16 + (lane >> 2);
#pragma unroll
    for (int nf = 0; nf < 32; nf++) {
        int c0 = nf * 8 + (lane & 3) * 2;
        *(__nv_bfloat162*)(gout + (size_t)row0 * CDIM + c0) =
            __floats2bfloat162_rn(O[nf][0] * inv0, O[nf][1] * inv0);
        *(__nv_bfloat162*)(gout + (size_t)(row0 + 8) * CDIM + c0) =
            __floats2bfloat162_rn(O[nf][2] * inv1, O[nf][3] * inv1);
    }
}

// ---------------- host ----------------
extern "C" void kernel_launch(void* const* d_in, const int* in_sizes, int n_in,
                              void* d_out, int out_size)
{
    const float* query  = (const float*)d_in[0];
    const float* key    = (const float*)d_in[1];
    const float* value  = (const float*)d_in[2];
    const float* ln_q_g = (const float*)d_in[3];
    const float* ln_q_b = (const float*)d_in[4];
    const float* Wq     = (const float*)d_in[5];
    const float* bq     = (const float*)d_in[6];
    const float* Wk     = (const float*)d_in[7];
    const float* Wv     = (const float*)d_in[8];
    const float* bv     = (const float*)d_in[9];
    const float* Wsem   = (const float*)d_in[10];
    const float* bsem   = (const float*)d_in[11];
    const float* Wproj  = (const float*)d_in[12];
    const float* bproj  = (const float*)d_in[13];
    const float* ln_f_g = (const float*)d_in[14];
    const float* ln_f_b = (const float*)d_in[15];
    const float* W1     = (const float*)d_in[16];
    const float* b1     = (const float*)d_in[17];
    const float* W2     = (const float*)d_in[18];
    const float* b2     = (const float*)d_in[19];

    void* sp = nullptr;
    cudaGetSymbolAddress(&sp, g_scratch);
    float* S    = (float*)sp;
    float* X    = S + OFF_X;
    float* X2   = S + OFF_X2;
    float* Y    = S + OFF_Y;
    float* SEM  = S + OFF_SEM;
    __nv_bfloat16* LNB  = (__nv_bfloat16*)(S + OFF_LNB);
    __nv_bfloat16* QB   = (__nv_bfloat16*)(S + OFF_QB);
    __nv_bfloat16* ATTB = (__nv_bfloat16*)(S + OFF_ATTB);
    __nv_bfloat16* HB   = (__nv_bfloat16*)(S + OFF_HB);
    __nv_bfloat16* KEYB = (__nv_bfloat16*)(S + OFF_KEYB);
    __nv_bfloat16* VALB = (__nv_bfloat16*)(S + OFF_VALB);
    __nv_bfloat16* KB   = (__nv_bfloat16*)(S + OFF_KB);
    __nv_bfloat16* VB   = (__nv_bfloat16*)(S + OFF_VB);
    __nv_bfloat16* WB   = (__nv_bfloat16*)(S + OFF_WB);
    __nv_bfloat16* WqB    = WB;
    __nv_bfloat16* WkB    = WB + 65536;
    __nv_bfloat16* WvB    = WB + 131072;
    __nv_bfloat16* WprojB = WB + 196608;
    __nv_bfloat16* W1B    = WB + 262144;
    __nv_bfloat16* W2B    = WB + 524288;

    cudaFuncSetAttribute(fattn_k, cudaFuncAttributeMaxDynamicSharedMemorySize, ATT_SMEM);
    cudaFuncSetAttribute(mgemm_k<1>, cudaFuncAttributeMaxDynamicSharedMemorySize, GEMM_SMEM);
    cudaFuncSetAttribute(mgemm_k<3>, cudaFuncAttributeMaxDynamicSharedMemorySize, GEMM_SMEM);
    cudaFuncSetAttribute(mgemm_k<4>, cudaFuncAttributeMaxDynamicSharedMemorySize, GEMM_SMEM);
    cudaFuncSetAttribute(kvgemm_k, cudaFuncAttributeMaxDynamicSharedMemorySize, GEMM_SMEM);

    wcvt_k<<<768, 256>>>(Wq, Wk, Wv, Wproj, W1, W2, WB);
    kvsem_k<<<KROWS / 8, 256>>>(key, value, Wsem, bsem, KEYB, VALB, SEM);
    tq_ln_k<<<dim3(HWN / 32, BATCH), 256>>>(query, ln_q_g, ln_q_b, X, LNB);
    mgemm_k<1><<<dim3(CDIM / 128, MROWS / 128), 256, GEMM_SMEM>>>(
        LNB, WqB, bq, nullptr, nullptr, QB, MROWS, CDIM, CDIM);
    kvgemm_k<<<dim3(CDIM / 128, KROWS / 128, 2), 256, GEMM_SMEM>>>(
        KEYB, VALB, WkB, WvB, bv, KB, VB);
    // launch #6 -> ncu capture target
    fattn_k<<<dim3(HWN / 128, BATCH), 256, ATT_SMEM>>>(QB, KB, VB, SEM, ATTB);
    mgemm_k<3><<<dim3(CDIM / 128, MROWS / 128), 256, GEMM_SMEM>>>(
        ATTB, WprojB, bproj, X, X2, nullptr, MROWS, CDIM, CDIM);
    ln2_k<<<MROWS / 8, 256>>>(X2, ln_f_g, ln_f_b, LNB);
    mgemm_k<4><<<dim3(FDIM / 128, MROWS / 128), 256, GEMM_SMEM>>>(
        LNB, W1B, b1, nullptr, nullptr, HB, MROWS, FDIM, CDIM);
    mgemm_k<3><<<dim3(CDIM / 128, MROWS / 128), 256, GEMM_SMEM>>>(
        HB, W2B, b2, X2, Y, nullptr, MROWS, CDIM, FDIM);
    transpose_k<<<dim3(CDIM / 32, HWN / 32, BATCH), dim3(32, 8)>>>(Y, (float*)d_out,
                                                                   HWN, CDIM);
}

// round 12
// speedup vs baseline: 1.0138x; 1.0138x over previous
#include <cuda_runtime.h>
#include <cuda_bf16.h>

#define BATCH 2
#define CDIM  256
#define HWN   16384
#define NKEY  4224
#define FDIM  1024
#define NQC   (BATCH*HWN*CDIM)
#define NKC   (BATCH*NKEY*CDIM)
#define MROWS (BATCH*HWN)
#define KROWS (BATCH*NKEY)

#define OFF_X    0
#define OFF_X2   (OFF_X + NQC)
#define OFF_Y    (OFF_X2 + NQC)
#define OFF_SEM  (OFF_Y + NQC)
#define OFF_LNB  (OFF_SEM + BATCH*NKEY + 64)
#define OFF_QB   (OFF_LNB + NQC/2)
#define OFF_ATTB (OFF_QB + NQC/2)
#define OFF_HB   (OFF_ATTB + NQC/2)
#define OFF_KEYB (OFF_HB + (BATCH*HWN*FDIM)/2)
#define OFF_VALB (OFF_KEYB + NKC/2)
#define OFF_KB   (OFF_VALB + NKC/2)
#define OFF_VB   (OFF_KB + NKC/2)
#define OFF_WB   (OFF_VB + NKC/2)
#define SCRATCH_FLOATS (OFF_WB + 786432/2 + 64)

__device__ float g_scratch[SCRATCH_FLOATS];

// ---------------- PTX helpers (mma.sync only — sm_100 target, no tcgen05) ----
__device__ __forceinline__ unsigned smem_u32(const void* p) {
    return (unsigned)__cvta_generic_to_shared(p);
}
__device__ __forceinline__ void ldmx4(unsigned& r0, unsigned& r1, unsigned& r2,
                                      unsigned& r3, const void* p) {
    unsigned a = smem_u32(p);
    asm volatile("ldmatrix.sync.aligned.m8n8.x4.shared.b16 {%0,%1,%2,%3},[%4];\n"
                 : "=r"(r0), "=r"(r1), "=r"(r2), "=r"(r3) : "r"(a));
}
__device__ __forceinline__ void ldmx4t(unsigned& r0, unsigned& r1, unsigned& r2,
                                       unsigned& r3, const void* p) {
    unsigned a = smem_u32(p);
    asm volatile("ldmatrix.sync.aligned.m8n8.x4.trans.shared.b16 {%0,%1,%2,%3},[%4];\n"
                 : "=r"(r0), "=r"(r1), "=r"(r2), "=r"(r3) : "r"(a));
}
__device__ __forceinline__ void mma16816(float* c, const unsigned* a, const unsigned* b) {
    asm volatile("mma.sync.aligned.m16n8k16.row.col.f32.bf16.bf16.f32 "
                 "{%0,%1,%2,%3},{%4,%5,%6,%7},{%8,%9},{%0,%1,%2,%3};\n"
                 : "+f"(c[0]), "+f"(c[1]), "+f"(c[2]), "+f"(c[3])
                 : "r"(a[0]), "r"(a[1]), "r"(a[2]), "r"(a[3]), "r"(b[0]), "r"(b[1]));
}
__device__ __forceinline__ void cp16(void* dst, const void* src) {
    unsigned d = smem_u32(dst);
    asm volatile("cp.async.cg.shared.global [%0],[%1],16;\n" :: "r"(d), "l"(src));
}
__device__ __forceinline__ void cp_commit() {
    asm volatile("cp.async.commit_group;\n" ::: "memory");
}
template <int N>
__device__ __forceinline__ void cp_wait() {
    asm volatile("cp.async.wait_group %0;\n" :: "n"(N) : "memory");
}
__device__ __forceinline__ unsigned pack_bf2(float x, float y) {
    __nv_bfloat162 h = __floats2bfloat162_rn(x, y);
    return *reinterpret_cast<unsigned*>(&h);
}

// ---------------- elementwise kernels ----------------
__global__ void wcvt_k(const float* __restrict__ Wq, const float* __restrict__ Wk,
                       const float* __restrict__ Wv, const float* __restrict__ Wp,
                       const float* __restrict__ W1, const float* __restrict__ W2,
                       __nv_bfloat16* __restrict__ out)
{
    int i = (blockIdx.x * blockDim.x + threadIdx.x) * 4;
    if (i >= 786432) return;
    const float* src; int base;
    if      (i < 65536)  { src = Wq; base = 0; }
    else if (i < 131072) { src = Wk; base = 65536; }
    else if (i < 196608) { src = Wv; base = 131072; }
    else if (i < 262144) { src = Wp; base = 196608; }
    else if (i < 524288) { src = W1; base = 262144; }
    else                 { src = W2; base = 524288; }
    float4 v = *(const float4*)(src + (i - base));
    *(__nv_bfloat162*)(out + i)     = __floats2bfloat162_rn(v.x, v.y);
    *(__nv_bfloat162*)(out + i + 2) = __floats2bfloat162_rn(v.z, v.w);
}

__global__ void kvsem_k(const float* __restrict__ key, const float* __restrict__ value,
                        const float* __restrict__ Wsem, const float* __restrict__ bsem,
                        __nv_bfloat16* __restrict__ keyb, __nv_bfloat16* __restrict__ valb,
                        float* __restrict__ sem)
{
    int w = blockIdx.x * 8 + (threadIdx.x >> 5);
    int lane = threadIdx.x & 31;
    if (w >= KROWS) return;
    int c0 = lane * 8;
    float4 ws0 = *(const float4*)(Wsem + c0);
    float4 ws1 = *(const float4*)(Wsem + c0 + 4);
    {
        const float4* kr = (const float4*)(key + (size_t)w * CDIM + c0);
        float4 a = kr[0], b = kr[1];
        __nv_bfloat162* d = (__nv_bfloat162*)(keyb + (size_t)w * CDIM + c0);
        d[0] = __floats2bfloat162_rn(a.x, a.y);
        d[1] = __floats2bfloat162_rn(a.z, a.w);
        d[2] = __floats2bfloat162_rn(b.x, b.y);
        d[3] = __floats2bfloat162_rn(b.z, b.w);
    }
    {
        const float4* vr = (const float4*)(value + (size_t)w * CDIM + c0);
        float4 a = vr[0], b = vr[1];
        __nv_bfloat162* d = (__nv_bfloat162*)(valb + (size_t)w * CDIM + c0);
        d[0] = __floats2bfloat162_rn(a.x, a.y);
        d[1] = __floats2bfloat162_rn(a.z, a.w);
        d[2] = __floats2bfloat162_rn(b.x, b.y);
        d[3] = __floats2bfloat162_rn(b.z, b.w);
        float acc = a.x * ws0.x + a.y * ws0.y + a.z * ws0.z + a.w * ws0.w
                  + b.x * ws1.x + b.y * ws1.y + b.z * ws1.z + b.w * ws1.w;
#pragma unroll
        for (int off = 16; off; off >>= 1)
            acc += __shfl_xor_sync(0xffffffffu, acc, off);
        if (lane == 0) sem[w] = acc + bsem[0];
    }
}

#define TQP 261
__global__ __launch_bounds__(256)
void tq_ln_k(const float* __restrict__ query, const float* __restrict__ g,
             const float* __restrict__ bb, float* __restrict__ X,
             __nv_bfloat16* __restrict__ LNB)
{
    __shared__ float sm[32][TQP];
    const int tx = threadIdx.x & 31, ty = threadIdx.x >> 5;
    const int b = blockIdx.y;
    const int n0 = blockIdx.x * 32;
    const float* qb = query + (size_t)b * CDIM * HWN;
#pragma unroll
    for (int i = 0; i < 8; i++)
#pragma unroll
        for (int j = 0; j < 4; j++) {
            int c = i * 32 + ty + j * 8;
            sm[tx][c] = qb[(size_t)c * HWN + n0 + tx];
        }
    __syncthreads();
    const int w = ty, lane = tx;
    float gv[8], bv[8];
#pragma unroll
    for (int j = 0; j < 8; j++) { gv[j] = g[lane * 8 + j]; bv[j] = bb[lane * 8 + j]; }
#pragma unroll
    for (int q = 0; q < 4; q++) {
        int nl = w * 4 + q;
        float v[8];
#pragma unroll
        for (int j = 0; j < 8; j++) v[j] = sm[nl][lane * 8 + j];
        float s = 0.f, s2 = 0.f;
#pragma unroll
        for (int j = 0; j < 8; j++) { s += v[j]; s2 += v[j] * v[j]; }
#pragma unroll
        for (int off = 16; off; off >>= 1) {
            s  += __shfl_xor_sync(0xffffffffu, s,  off);
            s2 += __shfl_xor_sync(0xffffffffu, s2, off);
        }
        float mu  = s * (1.f / CDIM);
        float var = s2 * (1.f / CDIM) - mu * mu;
        float rs  = rsqrtf(var + 1e-5f);
        size_t rowoff = (size_t)(b * HWN + n0 + nl) * CDIM + lane * 8;
        *(float4*)(X + rowoff)     = make_float4(v[0], v[1], v[2], v[3]);
        *(float4*)(X + rowoff + 4) = make_float4(v[4], v[5], v[6], v[7]);
        __nv_bfloat162* d = (__nv_bfloat162*)(LNB + rowoff);
#pragma unroll
        for (int j = 0; j < 4; j++) {
            float o0 = (v[2 * j]     - mu) * rs * gv[2 * j]     + bv[2 * j];
            float o1 = (v[2 * j + 1] - mu) * rs * gv[2 * j + 1] + bv[2 * j + 1];
            d[j] = __floats2bfloat162_rn(o0, o1);
        }
    }
}

__global__ void ln2_k(const float* __restrict__ in, const float* __restrict__ g,
                      const float* __restrict__ bb, __nv_bfloat16* __restrict__ out)
{
    int w = blockIdx.x * 8 + (threadIdx.x >> 5);
    int lane = threadIdx.x & 31;
    int c0 = lane * 8;
    const float4* ir = (const float4*)(in + (size_t)w * CDIM + c0);
    float4 a = ir[0], bq = ir[1];
    float v[8] = {a.x, a.y, a.z, a.w, bq.x, bq.y, bq.z, bq.w};
    float s = 0.f, s2 = 0.f;
#pragma unroll
    for (int j = 0; j < 8; j++) { s += v[j]; s2 += v[j] * v[j]; }
#pragma unroll
    for (int off = 16; off; off >>= 1) {
        s  += __shfl_xor_sync(0xffffffffu, s,  off);
        s2 += __shfl_xor_sync(0xffffffffu, s2, off);
    }
    float mu  = s * (1.f / CDIM);
    float var = s2 * (1.f / CDIM) - mu * mu;
    float rs  = rsqrtf(var + 1e-5f);
    __nv_bfloat162* d = (__nv_bfloat162*)(out + (size_t)w * CDIM + c0);
#pragma unroll
    for (int j = 0; j < 4; j++) {
        float o0 = (v[2 * j]     - mu) * rs * g[c0 + 2 * j]     + bb[c0 + 2 * j];
        float o1 = (v[2 * j + 1] - mu) * rs * g[c0 + 2 * j + 1] + bb[c0 + 2 * j + 1];
        d[j] = __floats2bfloat162_rn(o0, o1);
    }
}

__global__ void transpose_k(const float* __restrict__ in, float* __restrict__ out,
                            int R, int S)
{
    __shared__ float tile[32][33];
    const float* ip = in  + (size_t)blockIdx.z * R * S;
    float*       op = out + (size_t)blockIdx.z * R * S;
    int r0 = blockIdx.y * 32, s0 = blockIdx.x * 32;
    int tx = threadIdx.x, ty = threadIdx.y;
#pragma unroll
    for (int i = ty; i < 32; i += 8)
        tile[i][tx] = ip[(size_t)(r0 + i) * S + s0 + tx];
    __syncthreads();
#pragma unroll
    for (int i = ty; i < 32; i += 8)
        op[(size_t)(s0 + i) * R + r0 + tx] = tile[tx][i];
}

// ---------------- mma.sync GEMM (BM=BN=128, BK=64, 2-stage, 1 barrier/iter) ----
#define GAP   72
#define GBP   136
#define GEMM_AS_ELEMS (128 * GAP)
#define GEMM_BS_ELEMS (64 * GBP)
#define GEMM_SMEM ((2 * GEMM_AS_ELEMS + 2 * GEMM_BS_ELEMS) * 2)

template <int MODE>
__device__ __forceinline__
void mgemm_body(const __nv_bfloat16* __restrict__ A, const __nv_bfloat16* __restrict__ Bm,
                const float* __restrict__ bias, const float* __restrict__ resid,
                float* __restrict__ Cf, __nv_bfloat16* __restrict__ Cb,
                int M, int N, int K)
{
    extern __shared__ __nv_bfloat16 gsm[];
    __nv_bfloat16* As = gsm;
    __nv_bfloat16* Bs = gsm + 2 * GEMM_AS_ELEMS;

    const int tid  = threadIdx.x;
    const int lane = tid & 31, w = tid >> 5;
    const int wm = w >> 1, wn = w & 1;
    const int sub = lane >> 3, l8 = lane & 7;
    const int bm = blockIdx.y * 128, bn = blockIdx.x * 128;

    const int a_row  = wm * 32 + (sub & 1) * 8 + l8;
    const int a_csel = (sub >> 1) * 8;
    const int b_rsel = (sub & 1) * 8 + l8;
    const int b_csel = wn * 64 + (sub >> 1) * 8;

    float C[2][8][4];
#pragma unroll
    for (int i = 0; i < 2; i++)
#pragma unroll
        for (int j = 0; j < 8; j++)
#pragma unroll
            for (int q = 0; q < 4; q++) C[i][j][q] = 0.f;

    const int KT = K / 64;
    auto load_stage = [&](int s, int k0) {
        __nv_bfloat16* Ast = As + s * GEMM_AS_ELEMS;
        __nv_bfloat16* Bst = Bs + s * GEMM_BS_ELEMS;
#pragma unroll
        for (int i = 0; i < 4; i++) {
            int ch = tid + i * 256;
            int ar = ch >> 3, ac = (ch & 7) * 8;
            cp16(&Ast[ar * GAP + ac], A + (size_t)(bm + ar) * K + k0 + ac);
        }
#pragma unroll
        for (int i = 0; i < 4; i++) {
            int ch = tid + i * 256;
            int br = ch >> 4, bc = (ch & 15) * 8;
            cp16(&Bst[br * GBP + bc], Bm + (size_t)(k0 + br) * N + bn + bc);
        }
    };

    // prologue: stage 0 loaded + published
    load_stage(0, 0);
    cp_commit();
    cp_wait<0>();
    __syncthreads();

    for (int kt = 0; kt < KT; kt++) {
        // issue next-stage loads (target buffer last read before the barrier
        // that ended iteration kt-1 -> safe to overwrite)
        if (kt + 1 < KT) { load_stage((kt + 1) & 1, (kt + 1) * 64); cp_commit(); }

        const __nv_bfloat16* Ast = As + (kt & 1) * GEMM_AS_ELEMS;
        const __nv_bfloat16* Bst = Bs + (kt & 1) * GEMM_BS_ELEMS;
#pragma unroll
        for (int kf = 0; kf < 4; kf++) {
            unsigned a[2][4];
#pragma unroll
            for (int mf = 0; mf < 2; mf++)
                ldmx4(a[mf][0], a[mf][1], a[mf][2], a[mf][3],
                      &Ast[(a_row + mf * 16) * GAP + kf * 16 + a_csel]);
            unsigned b[8][2];
#pragma unroll
            for (int nb = 0; nb < 4; nb++) {
                unsigned r0, r1, r2, r3;
                ldmx4t(r0, r1, r2, r3, &Bst[(kf * 16 + b_rsel) * GBP + b_csel + nb * 16]);
                b[2 * nb][0] = r0; b[2 * nb][1] = r1;
                b[2 * nb + 1][0] = r2; b[2 * nb + 1][1] = r3;
            }
#pragma unroll
            for (int mf = 0; mf < 2; mf++)
#pragma unroll
                for (int nf = 0; nf < 8; nf++)
                    mma16816(C[mf][nf], a[mf], b[nf]);
        }

        // single barrier: publishes stage kt+1 to all warps AND closes the
        // read window on stage kt before iteration kt+1 overwrites kt-1's slot
        if (kt + 1 < KT) { cp_wait<0>(); __syncthreads(); }
    }

    // epilogue (no smem use -> no final barrier needed)
#pragma unroll
    for (int mf = 0; mf < 2; mf++) {
        int row0 = bm + wm * 32 + mf * 16 + (lane >> 2);
#pragma unroll
        for (int nf = 0; nf < 8; nf++) {
            int col = bn + wn * 64 + nf * 8 + (lane & 3) * 2;
            float b0 = bias ? bias[col] : 0.f;
            float b1 = bias ? bias[col + 1] : 0.f;
#pragma unroll
            for (int half = 0; half < 2; half++) {
                int row = row0 + half * 8;
                float v0 = C[mf][nf][2 * half]     + b0;
                float v1 = C[mf][nf][2 * half + 1] + b1;
                if (MODE == 3) {
                    float2 r = *(const float2*)(resid + (size_t)row * N + col);
                    v0 += r.x; v1 += r.y;
                    *(float2*)(Cf + (size_t)row * N + col) = make_float2(v0, v1);
                } else if (MODE == 4) {
                    v0 = 0.5f * v0 * (1.f + erff(v0 * 0.70710678118654752f));
                    v1 = 0.5f * v1 * (1.f + erff(v1 * 0.70710678118654752f));
                    *(__nv_bfloat162*)(Cb + (size_t)row * N + col) = __floats2bfloat162_rn(v0, v1);
                } else {
                    *(__nv_bfloat162*)(Cb + (size_t)row * N + col) = __floats2bfloat162_rn(v0, v1);
                }
            }
        }
    }
}

template <int MODE>
__global__ __launch_bounds__(256)
void mgemm_k(const __nv_bfloat16* __restrict__ A, const __nv_bfloat16* __restrict__ Bm,
             const float* __restrict__ bias, const float* __restrict__ resid,
             float* __restrict__ Cf, __nv_bfloat16* __restrict__ Cb,
             int M, int N, int K)
{
    mgemm_body<MODE>(A, Bm, bias, resid, Cf, Cb, M, N, K);
}

__global__ __launch_bounds__(256)
void kvgemm_k(const __nv_bfloat16* __restrict__ A0, const __nv_bfloat16* __restrict__ A1,
              const __nv_bfloat16* __restrict__ B0, const __nv_bfloat16* __restrict__ B1,
              const float* __restrict__ bias1,
              __nv_bfloat16* __restrict__ C0, __nv_bfloat16* __restrict__ C1)
{
    if (blockIdx.z == 0)
        mgemm_body<1>(A0, B0, nullptr, nullptr, nullptr, C0, KROWS, CDIM, CDIM);
    else
        mgemm_body<1>(A1, B1, bias1, nullptr, nullptr, C1, KROWS, CDIM, CDIM);
}

// ---------------------------------------------------------------------------
// Flash attention (mma.sync, MAX-FREE softmax), single barrier per tile.
// Br=128 (8 warps x 16 rows), Bc=64, d=256. K/V + sem double-buffered.
// ---------------------------------------------------------------------------
#define APITCH 264
#define QELEMS (128 * APITCH)
#define KVELEMS (64 * APITCH)
#define ATT_SMEM ((QELEMS + 4 * KVELEMS) * 2 + 2 * 64 * 4)

__global__ __launch_bounds__(256, 1)
void fattn_k(const __nv_bfloat16* __restrict__ gq, const __nv_bfloat16* __restrict__ gk,
             const __nv_bfloat16* __restrict__ gv, const float* __restrict__ gsem,
             __nv_bfloat16* __restrict__ gout)
{
    extern __shared__ char smraw[];
    __nv_bfloat16* Qs = (__nv_bfloat16*)smraw;
    __nv_bfloat16* Ks = Qs + QELEMS;                  // [2][64][APITCH]
    __nv_bfloat16* Vs = Ks + 2 * KVELEMS;             // [2][64][APITCH]
    float*         semS = (float*)(Vs + 2 * KVELEMS); // [2][64]

    const int tid  = threadIdx.x;
    const int lane = tid & 31, w = tid >> 5;
    const int sub  = lane >> 3, l8 = lane & 7;
    const int b    = blockIdx.y;
    const int qrow0 = b * HWN + blockIdx.x * 128;

    const int q_row  = w * 16 + (sub & 1) * 8 + l8;
    const int q_csel = (sub >> 1) * 8;
    const int k_rsel = (sub & 1) * 8 + l8;
    const int k_csel = (sub >> 1) * 8;

    // prologue: Q + stage 0 of K/V + sem, then publish
#pragma unroll
    for (int i = 0; i < 16; i++) {
        int ch = tid + i * 256;
        int r = ch >> 5, c = (ch & 31) * 8;
        cp16(&Qs[r * APITCH + c], gq + (size_t)(qrow0 + r) * CDIM + c);
    }
    const size_t kvbase = (size_t)b * NKEY;
#pragma unroll
    for (int i = 0; i < 8; i++) {
        int ch = tid + i * 256;
        int r = ch >> 5, c = (ch & 31) * 8;
        cp16(&Ks[r * APITCH + c], gk + (kvbase + r) * CDIM + c);
        cp16(&Vs[r * APITCH + c], gv + (kvbase + r) * CDIM + c);
    }
    if (tid < 16) cp16(&semS[tid * 4], gsem + kvbase + tid * 4);
    cp_commit();
    cp_wait<0>();
    __syncthreads();

    float O[32][4];
#pragma unroll
    for (int i = 0; i < 32; i++)
#pragma unroll
        for (int j = 0; j < 4; j++) O[i][j] = 0.f;
    float l0 = 0.f, l1 = 0.f;

    const int T = NKEY / 64;   // 66
    for (int t = 0; t < T; t++) {
        const int s = t & 1;
        // issue next tile's loads (other buffer; last read before the barrier
        // that ended iteration t-1)
        if (t + 1 < T) {
            const int s2 = (t + 1) & 1;
            const size_t rb = kvbase + (size_t)(t + 1) * 64;
#pragma unroll
            for (int i = 0; i < 8; i++) {
                int ch = tid + i * 256;
                int r = ch >> 5, c = (ch & 31) * 8;
                cp16(&Ks[s2 * KVELEMS + r * APITCH + c], gk + (rb + r) * CDIM + c);
                cp16(&Vs[s2 * KVELEMS + r * APITCH + c], gv + (rb + r) * CDIM + c);
            }
            if (tid < 16) cp16(&semS[s2 * 64 + tid * 4], gsem + rb + tid * 4);
            cp_commit();
        }

        // ---- S = Q @ K^T ----
        float S[8][4];
#pragma unroll
        for (int i = 0; i < 8; i++)
#pragma unroll
            for (int j = 0; j < 4; j++) S[i][j] = 0.f;
        const __nv_bfloat16* Kt = Ks + s * KVELEMS;
#pragma unroll
        for (int kf = 0; kf < 16; kf++) {
            unsigned a[4];
            ldmx4(a[0], a[1], a[2], a[3], &Qs[q_row * APITCH + kf * 16 + q_csel]);
#pragma unroll
            for (int nb = 0; nb < 4; nb++) {
                unsigned r0, r1, r2, r3;
                ldmx4(r0, r1, r2, r3,
                      &Kt[(nb * 16 + k_rsel) * APITCH + kf * 16 + k_csel]);
                unsigned bA[2] = {r0, r2};
                unsigned bB[2] = {r1, r3};
                mma16816(S[2 * nb], a, bA);
                mma16816(S[2 * nb + 1], a, bB);
            }
        }

        // ---- max-free softmax ----
        const float* semT = semS + s * 64;
        unsigned PA[4][4];
#pragma unroll
        for (int kf = 0; kf < 4; kf++) {
            int c0a = (2 * kf) * 8 + (lane & 3) * 2;
            int c0b = (2 * kf + 1) * 8 + (lane & 3) * 2;
            float p00 = __expf(S[2 * kf][0] * 0.0625f + semT[c0a]);
            float p01 = __expf(S[2 * kf][1] * 0.0625f + semT[c0a + 1]);
            float p02 = __expf(S[2 * kf][2] * 0.0625f + semT[c0a]);
            float p03 = __expf(S[2 * kf][3] * 0.0625f + semT[c0a + 1]);
            float p10 = __expf(S[2 * kf + 1][0] * 0.0625f + semT[c0b]);
            float p11 = __expf(S[2 * kf + 1][1] * 0.0625f + semT[c0b + 1]);
            float p12 = __expf(S[2 * kf + 1][2] * 0.0625f + semT[c0b]);
            float p13 = __expf(S[2 * kf + 1][3] * 0.0625f + semT[c0b + 1]);
            l0 += p00 + p01 + p10 + p11;
            l1 += p02 + p03 + p12 + p13;
            PA[kf][0] = pack_bf2(p00, p01);
            PA[kf][1] = pack_bf2(p02, p03);
            PA[kf][2] = pack_bf2(p10, p11);
            PA[kf][3] = pack_bf2(p12, p13);
        }

        // ---- O += P @ V ----
        const __nv_bfloat16* Vt = Vs + s * KVELEMS;
#pragma unroll
        for (int db = 0; db < 16; db++) {
#pragma unroll
            for (int kf = 0; kf < 4; kf++) {
                unsigned r0, r1, r2, r3;
                ldmx4t(r0, r1, r2, r3,
                       &Vt[(kf * 16 + k_rsel) * APITCH + db * 16 + k_csel]);
                unsigned bA[2] = {r0, r1};
                unsigned bB[2] = {r2, r3};
                mma16816(O[2 * db], PA[kf], bA);
                mma16816(O[2 * db + 1], PA[kf], bB);
            }
        }

        // single barrier: publishes stage t+1 AND closes the read window on
        // stage t before iteration t+1 issues loads over t-1's slot
        if (t + 1 < T) { cp_wait<0>(); __syncthreads(); }
    }

    // epilogue
    l0 += __shfl_xor_sync(0xffffffffu, l0, 1);
    l0 += __shfl_xor_sync(0xffffffffu, l0, 2);
    l1 += __shfl_xor_sync(0xffffffffu, l1, 1);
    l1 += __shfl_xor_sync(0xffffffffu, l1, 2);
    float inv0 = 1.f / l0, inv1 = 1.f / l1;
    int row0 = qrow0 + w * 16 + (lane >> 2);
#pragma unroll
    for (int nf = 0; nf < 32; nf++) {
        int c0 = nf * 8 + (lane & 3) * 2;
        *(__nv_bfloat162*)(gout + (size_t)row0 * CDIM + c0) =
            __floats2bfloat162_rn(O[nf][0] * inv0, O[nf][1] * inv0);
        *(__nv_bfloat162*)(gout + (size_t)(row0 + 8) * CDIM + c0) =
            __floats2bfloat162_rn(O[nf][2] * inv1, O[nf][3] * inv1);
    }
}

// ---------------- host ----------------
extern "C" void kernel_launch(void* const* d_in, const int* in_sizes, int n_in,
                              void* d_out, int out_size)
{
    const float* query  = (const float*)d_in[0];
    const float* key    = (const float*)d_in[1];
    const float* value  = (const float*)d_in[2];
    const float* ln_q_g = (const float*)d_in[3];
    const float* ln_q_b = (const float*)d_in[4];
    const float* Wq     = (const float*)d_in[5];
    const float* bq     = (const float*)d_in[6];
    const float* Wk     = (const float*)d_in[7];
    const float* Wv     = (const float*)d_in[8];
    const float* bv     = (const float*)d_in[9];
    const float* Wsem   = (const float*)d_in[10];
    const float* bsem   = (const float*)d_in[11];
    const float* Wproj  = (const float*)d_in[12];
    const float* bproj  = (const float*)d_in[13];
    const float* ln_f_g = (const float*)d_in[14];
    const float* ln_f_b = (const float*)d_in[15];
    const float* W1     = (const float*)d_in[16];
    const float* b1     = (const float*)d_in[17];
    const float* W2     = (const float*)d_in[18];
    const float* b2     = (const float*)d_in[19];

    void* sp = nullptr;
    cudaGetSymbolAddress(&sp, g_scratch);
    float* S    = (float*)sp;
    float* X    = S + OFF_X;
    float* X2   = S + OFF_X2;
    float* Y    = S + OFF_Y;
    float* SEM  = S + OFF_SEM;
    __nv_bfloat16* LNB  = (__nv_bfloat16*)(S + OFF_LNB);
    __nv_bfloat16* QB   = (__nv_bfloat16*)(S + OFF_QB);
    __nv_bfloat16* ATTB = (__nv_bfloat16*)(S + OFF_ATTB);
    __nv_bfloat16* HB   = (__nv_bfloat16*)(S + OFF_HB);
    __nv_bfloat16* KEYB = (__nv_bfloat16*)(S + OFF_KEYB);
    __nv_bfloat16* VALB = (__nv_bfloat16*)(S + OFF_VALB);
    __nv_bfloat16* KB   = (__nv_bfloat16*)(S + OFF_KB);
    __nv_bfloat16* VB   = (__nv_bfloat16*)(S + OFF_VB);
    __nv_bfloat16* WB   = (__nv_bfloat16*)(S + OFF_WB);
    __nv_bfloat16* WqB    = WB;
    __nv_bfloat16* WkB    = WB + 65536;
    __nv_bfloat16* WvB    = WB + 131072;
    __nv_bfloat16* WprojB = WB + 196608;
    __nv_bfloat16* W1B    = WB + 262144;
    __nv_bfloat16* W2B    = WB + 524288;

    cudaFuncSetAttribute(fattn_k, cudaFuncAttributeMaxDynamicSharedMemorySize, ATT_SMEM);
    cudaFuncSetAttribute(mgemm_k<1>, cudaFuncAttributeMaxDynamicSharedMemorySize, GEMM_SMEM);
    cudaFuncSetAttribute(mgemm_k<3>, cudaFuncAttributeMaxDynamicSharedMemorySize, GEMM_SMEM);
    cudaFuncSetAttribute(mgemm_k<4>, cudaFuncAttributeMaxDynamicSharedMemorySize, GEMM_SMEM);
    cudaFuncSetAttribute(kvgemm_k, cudaFuncAttributeMaxDynamicSharedMemorySize, GEMM_SMEM);

    wcvt_k<<<768, 256>>>(Wq, Wk, Wv, Wproj, W1, W2, WB);
    kvsem_k<<<KROWS / 8, 256>>>(key, value, Wsem, bsem, KEYB, VALB, SEM);
    tq_ln_k<<<dim3(HWN / 32, BATCH), 256>>>(query, ln_q_g, ln_q_b, X, LNB);
    mgemm_k<1><<<dim3(CDIM / 128, MROWS / 128), 256, GEMM_SMEM>>>(
        LNB, WqB, bq, nullptr, nullptr, QB, MROWS, CDIM, CDIM);
    kvgemm_k<<<dim3(CDIM / 128, KROWS / 128, 2), 256, GEMM_SMEM>>>(
        KEYB, VALB, WkB, WvB, bv, KB, VB);
    // launch #6 -> ncu capture target
    fattn_k<<<dim3(HWN / 128, BATCH), 256, ATT_SMEM>>>(QB, KB, VB, SEM, ATTB);
    mgemm_k<3><<<dim3(CDIM / 128, MROWS / 128), 256, GEMM_SMEM>>>(
        ATTB, WprojB, bproj, X, X2, nullptr, MROWS, CDIM, CDIM);
    ln2_k<<<MROWS / 8, 256>>>(X2, ln_f_g, ln_f_b, LNB);
    mgemm_k<4><<<dim3(FDIM / 128, MROWS / 128), 256, GEMM_SMEM>>>(
        LNB, W1B, b1, nullptr, nullptr, HB, MROWS, FDIM, CDIM);
    mgemm_k<3><<<dim3(CDIM / 128, MROWS / 128), 256, GEMM_SMEM>>>(
        HB, W2B, b2, X2, Y, nullptr, MROWS, CDIM, FDIM);
    transpose_k<<<dim3(CDIM / 32, HWN / 32, BATCH), dim3(32, 8)>>>(Y, (float*)d_out,
                                                                   HWN, CDIM);
}

// round 13
// speedup vs baseline: 1.0179x; 1.0041x over previous
#include <cuda_runtime.h>
#include <cuda_bf16.h>

#define BATCH 2
#define CDIM  256
#define HWN   16384
#define NKEY  4224
#define FDIM  1024
#define NQC   (BATCH*HWN*CDIM)
#define NKC   (BATCH*NKEY*CDIM)
#define MROWS (BATCH*HWN)
#define KROWS (BATCH*NKEY)

#define OFF_X    0
#define OFF_X2   (OFF_X + NQC)
#define OFF_Y    (OFF_X2 + NQC)
#define OFF_SEM  (OFF_Y + NQC)
#define OFF_LNB  (OFF_SEM + BATCH*NKEY + 64)
#define OFF_QB   (OFF_LNB + NQC/2)
#define OFF_ATTB (OFF_QB + NQC/2)
#define OFF_HB   (OFF_ATTB + NQC/2)
#define OFF_KEYB (OFF_HB + (BATCH*HWN*FDIM)/2)
#define OFF_VALB (OFF_KEYB + NKC/2)
#define OFF_KB   (OFF_VALB + NKC/2)
#define OFF_VB   (OFF_KB + NKC/2)
#define OFF_WB   (OFF_VB + NKC/2)
#define SCRATCH_FLOATS (OFF_WB + 786432/2 + 64)

__device__ float g_scratch[SCRATCH_FLOATS];

// ---------------- PTX helpers (mma.sync only — sm_100 target, no tcgen05) ----
__device__ __forceinline__ unsigned smem_u32(const void* p) {
    return (unsigned)__cvta_generic_to_shared(p);
}
__device__ __forceinline__ void ldmx4(unsigned& r0, unsigned& r1, unsigned& r2,
                                      unsigned& r3, const void* p) {
    unsigned a = smem_u32(p);
    asm volatile("ldmatrix.sync.aligned.m8n8.x4.shared.b16 {%0,%1,%2,%3},[%4];\n"
                 : "=r"(r0), "=r"(r1), "=r"(r2), "=r"(r3) : "r"(a));
}
__device__ __forceinline__ void ldmx4t(unsigned& r0, unsigned& r1, unsigned& r2,
                                       unsigned& r3, const void* p) {
    unsigned a = smem_u32(p);
    asm volatile("ldmatrix.sync.aligned.m8n8.x4.trans.shared.b16 {%0,%1,%2,%3},[%4];\n"
                 : "=r"(r0), "=r"(r1), "=r"(r2), "=r"(r3) : "r"(a));
}
__device__ __forceinline__ void mma16816(float* c, const unsigned* a, const unsigned* b) {
    asm volatile("mma.sync.aligned.m16n8k16.row.col.f32.bf16.bf16.f32 "
                 "{%0,%1,%2,%3},{%4,%5,%6,%7},{%8,%9},{%0,%1,%2,%3};\n"
                 : "+f"(c[0]), "+f"(c[1]), "+f"(c[2]), "+f"(c[3])
                 : "r"(a[0]), "r"(a[1]), "r"(a[2]), "r"(a[3]), "r"(b[0]), "r"(b[1]));
}
__device__ __forceinline__ void cp16(void* dst, const void* src) {
    unsigned d = smem_u32(dst);
    asm volatile("cp.async.cg.shared.global [%0],[%1],16;\n" :: "r"(d), "l"(src));
}
__device__ __forceinline__ void cp_commit() {
    asm volatile("cp.async.commit_group;\n" ::: "memory");
}
template <int N>
__device__ __forceinline__ void cp_wait() {
    asm volatile("cp.async.wait_group %0;\n" :: "n"(N) : "memory");
}
__device__ __forceinline__ unsigned pack_bf2(float x, float y) {
    __nv_bfloat162 h = __floats2bfloat162_rn(x, y);
    return *reinterpret_cast<unsigned*>(&h);
}

// ---------------- elementwise kernels ----------------
__global__ void wcvt_k(const float* __restrict__ Wq, const float* __restrict__ Wk,
                       const float* __restrict__ Wv, const float* __restrict__ Wp,
                       const float* __restrict__ W1, const float* __restrict__ W2,
                       __nv_bfloat16* __restrict__ out)
{
    int i = (blockIdx.x * blockDim.x + threadIdx.x) * 4;
    if (i >= 786432) return;
    const float* src; int base;
    if      (i < 65536)  { src = Wq; base = 0; }
    else if (i < 131072) { src = Wk; base = 65536; }
    else if (i < 196608) { src = Wv; base = 131072; }
    else if (i < 262144) { src = Wp; base = 196608; }
    else if (i < 524288) { src = W1; base = 262144; }
    else                 { src = W2; base = 524288; }
    float4 v = *(const float4*)(src + (i - base));
    *(__nv_bfloat162*)(out + i)     = __floats2bfloat162_rn(v.x, v.y);
    *(__nv_bfloat162*)(out + i + 2) = __floats2bfloat162_rn(v.z, v.w);
}

__global__ void kvsem_k(const float* __restrict__ key, const float* __restrict__ value,
                        const float* __restrict__ Wsem, const float* __restrict__ bsem,
                        __nv_bfloat16* __restrict__ keyb, __nv_bfloat16* __restrict__ valb,
                        float* __restrict__ sem)
{
    int w = blockIdx.x * 8 + (threadIdx.x >> 5);
    int lane = threadIdx.x & 31;
    if (w >= KROWS) return;
    int c0 = lane * 8;
    float4 ws0 = *(const float4*)(Wsem + c0);
    float4 ws1 = *(const float4*)(Wsem + c0 + 4);
    {
        const float4* kr = (const float4*)(key + (size_t)w * CDIM + c0);
        float4 a = kr[0], b = kr[1];
        __nv_bfloat162* d = (__nv_bfloat162*)(keyb + (size_t)w * CDIM + c0);
        d[0] = __floats2bfloat162_rn(a.x, a.y);
        d[1] = __floats2bfloat162_rn(a.z, a.w);
        d[2] = __floats2bfloat162_rn(b.x, b.y);
        d[3] = __floats2bfloat162_rn(b.z, b.w);
    }
    {
        const float4* vr = (const float4*)(value + (size_t)w * CDIM + c0);
        float4 a = vr[0], b = vr[1];
        __nv_bfloat162* d = (__nv_bfloat162*)(valb + (size_t)w * CDIM + c0);
        d[0] = __floats2bfloat162_rn(a.x, a.y);
        d[1] = __floats2bfloat162_rn(a.z, a.w);
        d[2] = __floats2bfloat162_rn(b.x, b.y);
        d[3] = __floats2bfloat162_rn(b.z, b.w);
        float acc = a.x * ws0.x + a.y * ws0.y + a.z * ws0.z + a.w * ws0.w
                  + b.x * ws1.x + b.y * ws1.y + b.z * ws1.z + b.w * ws1.w;
#pragma unroll
        for (int off = 16; off; off >>= 1)
            acc += __shfl_xor_sync(0xffffffffu, acc, off);
        if (lane == 0) sem[w] = acc + bsem[0];
    }
}

#define TQP 261
__global__ __launch_bounds__(256)
void tq_ln_k(const float* __restrict__ query, const float* __restrict__ g,
             const float* __restrict__ bb, float* __restrict__ X,
             __nv_bfloat16* __restrict__ LNB)
{
    __shared__ float sm[32][TQP];
    const int tx = threadIdx.x & 31, ty = threadIdx.x >> 5;
    const int b = blockIdx.y;
    const int n0 = blockIdx.x * 32;
    const float* qb = query + (size_t)b * CDIM * HWN;
#pragma unroll
    for (int i = 0; i < 8; i++)
#pragma unroll
        for (int j = 0; j < 4; j++) {
            int c = i * 32 + ty + j * 8;
            sm[tx][c] = qb[(size_t)c * HWN + n0 + tx];
        }
    __syncthreads();
    const int w = ty, lane = tx;
    float gv[8], bv[8];
#pragma unroll
    for (int j = 0; j < 8; j++) { gv[j] = g[lane * 8 + j]; bv[j] = bb[lane * 8 + j]; }
#pragma unroll
    for (int q = 0; q < 4; q++) {
        int nl = w * 4 + q;
        float v[8];
#pragma unroll
        for (int j = 0; j < 8; j++) v[j] = sm[nl][lane * 8 + j];
        float s = 0.f, s2 = 0.f;
#pragma unroll
        for (int j = 0; j < 8; j++) { s += v[j]; s2 += v[j] * v[j]; }
#pragma unroll
        for (int off = 16; off; off >>= 1) {
            s  += __shfl_xor_sync(0xffffffffu, s,  off);
            s2 += __shfl_xor_sync(0xffffffffu, s2, off);
        }
        float mu  = s * (1.f / CDIM);
        float var = s2 * (1.f / CDIM) - mu * mu;
        float rs  = rsqrtf(var + 1e-5f);
        size_t rowoff = (size_t)(b * HWN + n0 + nl) * CDIM + lane * 8;
        *(float4*)(X + rowoff)     = make_float4(v[0], v[1], v[2], v[3]);
        *(float4*)(X + rowoff + 4) = make_float4(v[4], v[5], v[6], v[7]);
        __nv_bfloat162* d = (__nv_bfloat162*)(LNB + rowoff);
#pragma unroll
        for (int j = 0; j < 4; j++) {
            float o0 = (v[2 * j]     - mu) * rs * gv[2 * j]     + bv[2 * j];
            float o1 = (v[2 * j + 1] - mu) * rs * gv[2 * j + 1] + bv[2 * j + 1];
            d[j] = __floats2bfloat162_rn(o0, o1);
        }
    }
}

__global__ void ln2_k(const float* __restrict__ in, const float* __restrict__ g,
                      const float* __restrict__ bb, __nv_bfloat16* __restrict__ out)
{
    int w = blockIdx.x * 8 + (threadIdx.x >> 5);
    int lane = threadIdx.x & 31;
    int c0 = lane * 8;
    const float4* ir = (const float4*)(in + (size_t)w * CDIM + c0);
    float4 a = ir[0], bq = ir[1];
    float v[8] = {a.x, a.y, a.z, a.w, bq.x, bq.y, bq.z, bq.w};
    float s = 0.f, s2 = 0.f;
#pragma unroll
    for (int j = 0; j < 8; j++) { s += v[j]; s2 += v[j] * v[j]; }
#pragma unroll
    for (int off = 16; off; off >>= 1) {
        s  += __shfl_xor_sync(0xffffffffu, s,  off);
        s2 += __shfl_xor_sync(0xffffffffu, s2, off);
    }
    float mu  = s * (1.f / CDIM);
    float var = s2 * (1.f / CDIM) - mu * mu;
    float rs  = rsqrtf(var + 1e-5f);
    __nv_bfloat162* d = (__nv_bfloat162*)(out + (size_t)w * CDIM + c0);
#pragma unroll
    for (int j = 0; j < 4; j++) {
        float o0 = (v[2 * j]     - mu) * rs * g[c0 + 2 * j]     + bb[c0 + 2 * j];
        float o1 = (v[2 * j + 1] - mu) * rs * g[c0 + 2 * j + 1] + bb[c0 + 2 * j + 1];
        d[j] = __floats2bfloat162_rn(o0, o1);
    }
}

__global__ void transpose_k(const float* __restrict__ in, float* __restrict__ out,
                            int R, int S)
{
    __shared__ float tile[32][33];
    const float* ip = in  + (size_t)blockIdx.z * R * S;
    float*       op = out + (size_t)blockIdx.z * R * S;
    int r0 = blockIdx.y * 32, s0 = blockIdx.x * 32;
    int tx = threadIdx.x, ty = threadIdx.y;
#pragma unroll
    for (int i = ty; i < 32; i += 8)
        tile[i][tx] = ip[(size_t)(r0 + i) * S + s0 + tx];
    __syncthreads();
#pragma unroll
    for (int i = ty; i < 32; i += 8)
        op[(size_t)(s0 + i) * R + r0 + tx] = tile[tx][i];
}

// ---------------- mma.sync GEMM: BM=128, BN=64, BK=64, 128 thr, 4 CTAs/SM ----
#define GAP   72    // As pitch
#define GBP   72    // Bs pitch (64 + 8 pad)
#define GEMM_AS_ELEMS (128 * GAP)
#define GEMM_BS_ELEMS (64 * GBP)
#define GEMM_SMEM ((2 * GEMM_AS_ELEMS + 2 * GEMM_BS_ELEMS) * 2)   // 55296 B

template <int MODE>
__device__ __forceinline__
void mgemm_body(const __nv_bfloat16* __restrict__ A, const __nv_bfloat16* __restrict__ Bm,
                const float* __restrict__ bias, const float* __restrict__ resid,
                float* __restrict__ Cf, __nv_bfloat16* __restrict__ Cb,
                int M, int N, int K)
{
    extern __shared__ __nv_bfloat16 gsm[];
    __nv_bfloat16* As = gsm;                      // [2][128][GAP]
    __nv_bfloat16* Bs = gsm + 2 * GEMM_AS_ELEMS;  // [2][64][GBP]

    const int tid  = threadIdx.x;                 // 0..127
    const int lane = tid & 31, wm = tid >> 5;     // 4 warps, warp tile 32x64
    const int sub = lane >> 3, l8 = lane & 7;
    const int bm = blockIdx.y * 128, bn = blockIdx.x * 64;

    const int a_row  = wm * 32 + (sub & 1) * 8 + l8;
    const int a_csel = (sub >> 1) * 8;
    const int b_rsel = (sub & 1) * 8 + l8;
    const int b_csel = (sub >> 1) * 8;

    float C[2][8][4];
#pragma unroll
    for (int i = 0; i < 2; i++)
#pragma unroll
        for (int j = 0; j < 8; j++)
#pragma unroll
            for (int q = 0; q < 4; q++) C[i][j][q] = 0.f;

    const int KT = K / 64;
    auto load_stage = [&](int s, int k0) {
        __nv_bfloat16* Ast = As + s * GEMM_AS_ELEMS;
        __nv_bfloat16* Bst = Bs + s * GEMM_BS_ELEMS;
#pragma unroll
        for (int i = 0; i < 8; i++) {             // A: 1024 chunks (128x64)
            int ch = tid + i * 128;
            int ar = ch >> 3, ac = (ch & 7) * 8;
            cp16(&Ast[ar * GAP + ac], A + (size_t)(bm + ar) * K + k0 + ac);
        }
#pragma unroll
        for (int i = 0; i < 4; i++) {             // B: 512 chunks (64x64)
            int ch = tid + i * 128;
            int br = ch >> 3, bc = (ch & 7) * 8;
            cp16(&Bst[br * GBP + bc], Bm + (size_t)(k0 + br) * N + bn + bc);
        }
    };

    load_stage(0, 0);
    cp_commit();
    for (int kt = 0; kt < KT; kt++) {
        if (kt + 1 < KT) { load_stage((kt + 1) & 1, (kt + 1) * 64); cp_commit(); cp_wait<1>(); }
        else cp_wait<0>();
        __syncthreads();
        const __nv_bfloat16* Ast = As + (kt & 1) * GEMM_AS_ELEMS;
        const __nv_bfloat16* Bst = Bs + (kt & 1) * GEMM_BS_ELEMS;
#pragma unroll
        for (int kf = 0; kf < 4; kf++) {
            unsigned a[2][4];
#pragma unroll
            for (int mf = 0; mf < 2; mf++)
                ldmx4(a[mf][0], a[mf][1], a[mf][2], a[mf][3],
                      &Ast[(a_row + mf * 16) * GAP + kf * 16 + a_csel]);
            unsigned b[8][2];
#pragma unroll
            for (int nb = 0; nb < 4; nb++) {
                unsigned r0, r1, r2, r3;
                ldmx4t(r0, r1, r2, r3,
                       &Bst[(kf * 16 + b_rsel) * GBP + b_csel + nb * 16]);
                b[2 * nb][0] = r0; b[2 * nb][1] = r1;
                b[2 * nb + 1][0] = r2; b[2 * nb + 1][1] = r3;
            }
#pragma unroll
            for (int mf = 0; mf < 2; mf++)
#pragma unroll
                for (int nf = 0; nf < 8; nf++)
                    mma16816(C[mf][nf], a[mf], b[nf]);
        }
        __syncthreads();
    }

    // epilogue
#pragma unroll
    for (int mf = 0; mf < 2; mf++) {
        int row0 = bm + wm * 32 + mf * 16 + (lane >> 2);
#pragma unroll
        for (int nf = 0; nf < 8; nf++) {
            int col = bn + nf * 8 + (lane & 3) * 2;
            float b0 = bias ? bias[col] : 0.f;
            float b1 = bias ? bias[col + 1] : 0.f;
#pragma unroll
            for (int half = 0; half < 2; half++) {
                int row = row0 + half * 8;
                float v0 = C[mf][nf][2 * half]     + b0;
                float v1 = C[mf][nf][2 * half + 1] + b1;
                if (MODE == 3) {
                    float2 r = *(const float2*)(resid + (size_t)row * N + col);
                    v0 += r.x; v1 += r.y;
                    *(float2*)(Cf + (size_t)row * N + col) = make_float2(v0, v1);
                } else if (MODE == 4) {
                    v0 = 0.5f * v0 * (1.f + erff(v0 * 0.70710678118654752f));
                    v1 = 0.5f * v1 * (1.f + erff(v1 * 0.70710678118654752f));
                    *(__nv_bfloat162*)(Cb + (size_t)row * N + col) = __floats2bfloat162_rn(v0, v1);
                } else {
                    *(__nv_bfloat162*)(Cb + (size_t)row * N + col) = __floats2bfloat162_rn(v0, v1);
                }
            }
        }
    }
}

template <int MODE>
__global__ __launch_bounds__(128)
void mgemm_k(const __nv_bfloat16* __restrict__ A, const __nv_bfloat16* __restrict__ Bm,
             const float* __restrict__ bias, const float* __restrict__ resid,
             float* __restrict__ Cf, __nv_bfloat16* __restrict__ Cb,
             int M, int N, int K)
{
    mgemm_body<MODE>(A, Bm, bias, resid, Cf, Cb, M, N, K);
}

__global__ __launch_bounds__(128)
void kvgemm_k(const __nv_bfloat16* __restrict__ A0, const __nv_bfloat16* __restrict__ A1,
              const __nv_bfloat16* __restrict__ B0, const __nv_bfloat16* __restrict__ B1,
              const float* __restrict__ bias1,
              __nv_bfloat16* __restrict__ C0, __nv_bfloat16* __restrict__ C1)
{
    if (blockIdx.z == 0)
        mgemm_body<1>(A0, B0, nullptr, nullptr, nullptr, C0, KROWS, CDIM, CDIM);
    else
        mgemm_body<1>(A1, B1, bias1, nullptr, nullptr, C1, KROWS, CDIM, CDIM);
}

// ---------------------------------------------------------------------------
// Flash attention (mma.sync, MAX-FREE softmax). Br=128 (8 warps x 16 rows),
// Bc=64, d=256. Identical to the 780us-best version.
// ---------------------------------------------------------------------------
#define APITCH 264
#define QELEMS (128 * APITCH)
#define KVELEMS (64 * APITCH)
#define ATT_SMEM ((QELEMS + 4 * KVELEMS) * 2 + 2 * 64 * 4)

__global__ __launch_bounds__(256, 1)
void fattn_k(const __nv_bfloat16* __restrict__ gq, const __nv_bfloat16* __restrict__ gk,
             const __nv_bfloat16* __restrict__ gv, const float* __restrict__ gsem,
             __nv_bfloat16* __restrict__ gout)
{
    extern __shared__ char smraw[];
    __nv_bfloat16* Qs = (__nv_bfloat16*)smraw;
    __nv_bfloat16* Ks = Qs + QELEMS;
    __nv_bfloat16* Vs = Ks + 2 * KVELEMS;
    float*         semS = (float*)(Vs + 2 * KVELEMS);

    const int tid  = threadIdx.x;
    const int lane = tid & 31, w = tid >> 5;
    const int sub  = lane >> 3, l8 = lane & 7;
    const int b    = blockIdx.y;
    const int qrow0 = b * HWN + blockIdx.x * 128;

    const int q_row  = w * 16 + (sub & 1) * 8 + l8;
    const int q_csel = (sub >> 1) * 8;
    const int k_rsel = (sub & 1) * 8 + l8;
    const int k_csel = (sub >> 1) * 8;

#pragma unroll
    for (int i = 0; i < 16; i++) {
        int ch = tid + i * 256;
        int r = ch >> 5, c = (ch & 31) * 8;
        cp16(&Qs[r * APITCH + c], gq + (size_t)(qrow0 + r) * CDIM + c);
    }
    const size_t kvbase = (size_t)b * NKEY;
#pragma unroll
    for (int i = 0; i < 8; i++) {
        int ch = tid + i * 256;
        int r = ch >> 5, c = (ch & 31) * 8;
        cp16(&Ks[r * APITCH + c], gk + (kvbase + r) * CDIM + c);
        cp16(&Vs[r * APITCH + c], gv + (kvbase + r) * CDIM + c);
    }
    if (tid < 16) cp16(&semS[tid * 4], gsem + kvbase + tid * 4);
    cp_commit();

    float O[32][4];
#pragma unroll
    for (int i = 0; i < 32; i++)
#pragma unroll
        for (int j = 0; j < 4; j++) O[i][j] = 0.f;
    float l0 = 0.f, l1 = 0.f;

    const int T = NKEY / 64;   // 66
    for (int t = 0; t < T; t++) {
        const int s = t & 1;
        if (t + 1 < T) {
            const int s2 = (t + 1) & 1;
            const size_t rb = kvbase + (size_t)(t + 1) * 64;
#pragma unroll
            for (int i = 0; i < 8; i++) {
                int ch = tid + i * 256;
                int r = ch >> 5, c = (ch & 31) * 8;
                cp16(&Ks[s2 * KVELEMS + r * APITCH + c], gk + (rb + r) * CDIM + c);
                cp16(&Vs[s2 * KVELEMS + r * APITCH + c], gv + (rb + r) * CDIM + c);
            }
            if (tid < 16) cp16(&semS[s2 * 64 + tid * 4], gsem + rb + tid * 4);
            cp_commit();
            cp_wait<1>();
        } else {
            cp_wait<0>();
        }
        __syncthreads();

        float S[8][4];
#pragma unroll
        for (int i = 0; i < 8; i++)
#pragma unroll
            for (int j = 0; j < 4; j++) S[i][j] = 0.f;
        const __nv_bfloat16* Kt = Ks + s * KVELEMS;
#pragma unroll
        for (int kf = 0; kf < 16; kf++) {
            unsigned a[4];
            ldmx4(a[0], a[1], a[2], a[3], &Qs[q_row * APITCH + kf * 16 + q_csel]);
#pragma unroll
            for (int nb = 0; nb < 4; nb++) {
                unsigned r0, r1, r2, r3;
                ldmx4(r0, r1, r2, r3,
                      &Kt[(nb * 16 + k_rsel) * APITCH + kf * 16 + k_csel]);
                unsigned bA[2] = {r0, r2};
                unsigned bB[2] = {r1, r3};
                mma16816(S[2 * nb], a, bA);
                mma16816(S[2 * nb + 1], a, bB);
            }
        }

        const float* semT = semS + s * 64;
        unsigned PA[4][4];
#pragma unroll
        for (int kf = 0; kf < 4; kf++) {
            int c0a = (2 * kf) * 8 + (lane & 3) * 2;
            int c0b = (2 * kf + 1) * 8 + (lane & 3) * 2;
            float p00 = __expf(S[2 * kf][0] * 0.0625f + semT[c0a]);
            float p01 = __expf(S[2 * kf][1] * 0.0625f + semT[c0a + 1]);
            float p02 = __expf(S[2 * kf][2] * 0.0625f + semT[c0a]);
            float p03 = __expf(S[2 * kf][3] * 0.0625f + semT[c0a + 1]);
            float p10 = __expf(S[2 * kf + 1][0] * 0.0625f + semT[c0b]);
            float p11 = __expf(S[2 * kf + 1][1] * 0.0625f + semT[c0b + 1]);
            float p12 = __expf(S[2 * kf + 1][2] * 0.0625f + semT[c0b]);
            float p13 = __expf(S[2 * kf + 1][3] * 0.0625f + semT[c0b + 1]);
            l0 += p00 + p01 + p10 + p11;
            l1 += p02 + p03 + p12 + p13;
            PA[kf][0] = pack_bf2(p00, p01);
            PA[kf][1] = pack_bf2(p02, p03);
            PA[kf][2] = pack_bf2(p10, p11);
            PA[kf][3] = pack_bf2(p12, p13);
        }

        const __nv_bfloat16* Vt = Vs + s * KVELEMS;
#pragma unroll
        for (int db = 0; db < 16; db++) {
#pragma unroll
            for (int kf = 0; kf < 4; kf++) {
                unsigned r0, r1, r2, r3;
                ldmx4t(r0, r1, r2, r3,
                       &Vt[(kf * 16 + k_rsel) * APITCH + db * 16 + k_csel]);
                unsigned bA[2] = {r0, r1};
                unsigned bB[2] = {r2, r3};
                mma16816(O[2 * db], PA[kf], bA);
                mma16816(O[2 * db + 1], PA[kf], bB);
            }
        }
        __syncthreads();
    }

    l0 += __shfl_xor_sync(0xffffffffu, l0, 1);
    l0 += __shfl_xor_sync(0xffffffffu, l0, 2);
    l1 += __shfl_xor_sync(0xffffffffu, l1, 1);
    l1 += __shfl_xor_sync(0xffffffffu, l1, 2);
    float inv0 = 1.f / l0, inv1 = 1.f / l1;
    int row0 = qrow0 + w * 16 + (lane >> 2);
#pragma unroll
    for (int nf = 0; nf < 32; nf++) {
        int c0 = nf * 8 + (lane & 3) * 2;
        *(__nv_bfloat162*)(gout + (size_t)row0 * CDIM + c0) =
            __floats2bfloat162_rn(O[nf][0] * inv0, O[nf][1] * inv0);
        *(__nv_bfloat162*)(gout + (size_t)(row0 + 8) * CDIM + c0) =
            __floats2bfloat162_rn(O[nf][2] * inv1, O[nf][3] * inv1);
    }
}

// ---------------- host ----------------
extern "C" void kernel_launch(void* const* d_in, const int* in_sizes, int n_in,
                              void* d_out, int out_size)
{
    const float* query  = (const float*)d_in[0];
    const float* key    = (const float*)d_in[1];
    const float* value  = (const float*)d_in[2];
    const float* ln_q_g = (const float*)d_in[3];
    const float* ln_q_b = (const float*)d_in[4];
    const float* Wq     = (const float*)d_in[5];
    const float* bq     = (const float*)d_in[6];
    const float* Wk     = (const float*)d_in[7];
    const float* Wv     = (const float*)d_in[8];
    const float* bv     = (const float*)d_in[9];
    const float* Wsem   = (const float*)d_in[10];
    const float* bsem   = (const float*)d_in[11];
    const float* Wproj  = (const float*)d_in[12];
    const float* bproj  = (const float*)d_in[13];
    const float* ln_f_g = (const float*)d_in[14];
    const float* ln_f_b = (const float*)d_in[15];
    const float* W1     = (const float*)d_in[16];
    const float* b1     = (const float*)d_in[17];
    const float* W2     = (const float*)d_in[18];
    const float* b2     = (const float*)d_in[19];

    void* sp = nullptr;
    cudaGetSymbolAddress(&sp, g_scratch);
    float* S    = (float*)sp;
    float* X    = S + OFF_X;
    float* X2   = S + OFF_X2;
    float* Y    = S + OFF_Y;
    float* SEM  = S + OFF_SEM;
    __nv_bfloat16* LNB  = (__nv_bfloat16*)(S + OFF_LNB);
    __nv_bfloat16* QB   = (__nv_bfloat16*)(S + OFF_QB);
    __nv_bfloat16* ATTB = (__nv_bfloat16*)(S + OFF_ATTB);
    __nv_bfloat16* HB   = (__nv_bfloat16*)(S + OFF_HB);
    __nv_bfloat16* KEYB = (__nv_bfloat16*)(S + OFF_KEYB);
    __nv_bfloat16* VALB = (__nv_bfloat16*)(S + OFF_VALB);
    __nv_bfloat16* KB   = (__nv_bfloat16*)(S + OFF_KB);
    __nv_bfloat16* VB   = (__nv_bfloat16*)(S + OFF_VB);
    __nv_bfloat16* WB   = (__nv_bfloat16*)(S + OFF_WB);
    __nv_bfloat16* WqB    = WB;
    __nv_bfloat16* WkB    = WB + 65536;
    __nv_bfloat16* WvB    = WB + 131072;
    __nv_bfloat16* WprojB = WB + 196608;
    __nv_bfloat16* W1B    = WB + 262144;
    __nv_bfloat16* W2B    = WB + 524288;

    cudaFuncSetAttribute(fattn_k, cudaFuncAttributeMaxDynamicSharedMemorySize, ATT_SMEM);
    cudaFuncSetAttribute(mgemm_k<1>, cudaFuncAttributeMaxDynamicSharedMemorySize, GEMM_SMEM);
    cudaFuncSetAttribute(mgemm_k<3>, cudaFuncAttributeMaxDynamicSharedMemorySize, GEMM_SMEM);
    cudaFuncSetAttribute(mgemm_k<4>, cudaFuncAttributeMaxDynamicSharedMemorySize, GEMM_SMEM);
    cudaFuncSetAttribute(kvgemm_k, cudaFuncAttributeMaxDynamicSharedMemorySize, GEMM_SMEM);

    wcvt_k<<<768, 256>>>(Wq, Wk, Wv, Wproj, W1, W2, WB);
    kvsem_k<<<KROWS / 8, 256>>>(key, value, Wsem, bsem, KEYB, VALB, SEM);
    tq_ln_k<<<dim3(HWN / 32, BATCH), 256>>>(query, ln_q_g, ln_q_b, X, LNB);
    mgemm_k<1><<<dim3(CDIM / 64, MROWS / 128), 128, GEMM_SMEM>>>(
        LNB, WqB, bq, nullptr, nullptr, QB, MROWS, CDIM, CDIM);
    kvgemm_k<<<dim3(CDIM / 64, KROWS / 128, 2), 128, GEMM_SMEM>>>(
        KEYB, VALB, WkB, WvB, bv, KB, VB);
    // launch #6 -> ncu capture target
    fattn_k<<<dim3(HWN / 128, BATCH), 256, ATT_SMEM>>>(QB, KB, VB, SEM, ATTB);
    mgemm_k<3><<<dim3(CDIM / 64, MROWS / 128), 128, GEMM_SMEM>>>(
        ATTB, WprojB, bproj, X, X2, nullptr, MROWS, CDIM, CDIM);
    ln2_k<<<MROWS / 8, 256>>>(X2, ln_f_g, ln_f_b, LNB);
    mgemm_k<4><<<dim3(FDIM / 64, MROWS / 128), 128, GEMM_SMEM>>>(
        LNB, W1B, b1, nullptr, nullptr, HB, MROWS, FDIM, CDIM);
    mgemm_k<3><<<dim3(CDIM / 64, MROWS / 128), 128, GEMM_SMEM>>>(
        HB, W2B, b2, X2, Y, nullptr, MROWS, CDIM, FDIM);
    transpose_k<<<dim3(CDIM / 32, HWN / 32, BATCH), dim3(32, 8)>>>(Y, (float*)d_out,
                                                                   HWN, CDIM);
}